// round 14
// baseline (speedup 1.0000x reference)
#include <cuda_runtime.h>
#include <cuda_fp16.h>
#include <cstdint>

// Problem constants: BATCH=4096, IN=512, HID=16384, OUT=1000
#define B_BATCH 4096
#define K_IN    512
#define H_HID   16384
#define N_OUT   1000

// Coarse GEMM tiling (int8): CTA 128x256, warp tile 64x64, 8 warps (proven config)
#define BM 128
#define BN 256
#define BK 128
#define STAGES 4
#define THREADS 256
#define NCHUNK (K_IN / BK)   // 4 == STAGES: full prefetch

#define A_ST_BYTES (BM * BK)                  // 16384
#define B_ST_BYTES (BN * BK)                  // 32768
#define STAGE_BYTES (A_ST_BYTES + B_ST_BYTES) // 49152
#define GEMM_SMEM (STAGES * STAGE_BYTES)      // 196608

#define NGRP (H_HID / 4)     // 4096 groups of 4 columns per batch row
#define MARGIN 0.5f
#define CAP 1024

#define NSPLIT 4             // row-chunks for GEMM/refine overlap
#define RT_PER (32 / NSPLIT) // 8 row-tiles per chunk

// ---------------- device scratch (static; no allocs) ----------------
__device__ int8_t g_xq[(size_t)B_BATCH * K_IN];            // 2 MB
__device__ int8_t g_wq[(size_t)H_HID * K_IN];              // 8 MB
__device__ float  g_dx[B_BATCH];
__device__ float  g_dw[H_HID];
__device__ __half g_gmin[(size_t)B_BATCH * NGRP];          // 32 MB: per-4col group minima
__device__ float  g_w2[H_HID];

// ---------------- overlap resources (created once at static init; host-side) ----------------
struct OverlapRes {
    cudaStream_t s2 = nullptr;
    cudaEvent_t  evFork[NSPLIT] = {};
    cudaEvent_t  evJoin = nullptr;
    bool ok = false;
    OverlapRes() {
        if (cudaStreamCreateWithFlags(&s2, cudaStreamNonBlocking) != cudaSuccess) return;
        for (int i = 0; i < NSPLIT; i++)
            if (cudaEventCreateWithFlags(&evFork[i], cudaEventDisableTiming) != cudaSuccess)
                return;
        if (cudaEventCreateWithFlags(&evJoin, cudaEventDisableTiming) != cudaSuccess) return;
        ok = true;
    }
};
static OverlapRes g_res;

// ---------------- helpers ----------------
__device__ __forceinline__ uint32_t smem_u32(const void* p) {
    uint32_t a;
    asm("{ .reg .u64 t; cvta.to.shared.u64 t, %1; cvt.u32.u64 %0, t; }" : "=r"(a) : "l"(p));
    return a;
}
__device__ __forceinline__ void cp_async16(uint32_t dst, const void* src) {
    asm volatile("cp.async.cg.shared.global [%0], [%1], 16;" :: "r"(dst), "l"(src) : "memory");
}
__device__ __forceinline__ void cp_commit() {
    asm volatile("cp.async.commit_group;" ::: "memory");
}
template <int N>
__device__ __forceinline__ void cp_wait() {
    asm volatile("cp.async.wait_group %0;" :: "n"(N) : "memory");
}
__device__ __forceinline__ void ldsm_x4(uint32_t* r, uint32_t addr) {
    asm volatile("ldmatrix.sync.aligned.m8n8.x4.shared.b16 {%0,%1,%2,%3}, [%4];"
                 : "=r"(r[0]), "=r"(r[1]), "=r"(r[2]), "=r"(r[3]) : "r"(addr));
}
__device__ __forceinline__ void mma16832s8(int* c, const uint32_t* a, const uint32_t* b) {
    asm volatile(
        "mma.sync.aligned.m16n8k32.row.col.s32.s8.s8.s32 "
        "{%0,%1,%2,%3}, {%4,%5,%6,%7}, {%8,%9}, {%0,%1,%2,%3};"
        : "+r"(c[0]), "+r"(c[1]), "+r"(c[2]), "+r"(c[3])
        : "r"(a[0]), "r"(a[1]), "r"(a[2]), "r"(a[3]), "r"(b[0]), "r"(b[1]));
}
__device__ __forceinline__ unsigned int f32_key(float f) {
    unsigned int u = __float_as_uint(f);
    return u ^ ((u & 0x80000000u) ? 0xFFFFFFFFu : 0x80000000u);
}
__device__ __forceinline__ uint32_t pack4(float a, float b, float c, float d, float sx) {
    int ia = __float2int_rn(fminf(fmaxf(a * sx, -127.f), 127.f));
    int ib = __float2int_rn(fminf(fmaxf(b * sx, -127.f), 127.f));
    int ic = __float2int_rn(fminf(fmaxf(c * sx, -127.f), 127.f));
    int id = __float2int_rn(fminf(fmaxf(d * sx, -127.f), 127.f));
    return (ia & 0xFF) | ((ib & 0xFF) << 8) | ((ic & 0xFF) << 16) | ((id & 0xFF) << 24);
}
// storage half-index -> base column of its 4-col group (epilogue packing inverse)
__device__ __forceinline__ int group_colbase(int hidx) {
    int tile = hidx >> 6, t = hidx & 63;
    int wn = t >> 4, r = t & 15;
    int p = r >> 3, nj = r & 7;
    return tile * 256 + wn * 64 + nj * 8 + p * 4;
}

// ---------------- prep (merged): int8 quantize X and W rows (+ exact w2 for W) ----------------
__global__ void prep_kernel(const float* __restrict__ X, const float* __restrict__ W) {
    int warp = threadIdx.x >> 5, lane = threadIdx.x & 31;
    bool is_x = blockIdx.x < (B_BATCH / 8);
    int row = (is_x ? blockIdx.x : blockIdx.x - B_BATCH / 8) * 8 + warp;
    const float* src = is_x ? X : W;
    const float4* p = reinterpret_cast<const float4*>(src + (size_t)row * K_IN);
    float4 v[4];
    float s = 0.f, mx = 0.f;
    #pragma unroll
    for (int i = 0; i < 4; i++) {
        v[i] = p[lane + i * 32];
        s += v[i].x * v[i].x + v[i].y * v[i].y + v[i].z * v[i].z + v[i].w * v[i].w;
        mx = fmaxf(mx, fmaxf(fmaxf(fabsf(v[i].x), fabsf(v[i].y)),
                             fmaxf(fabsf(v[i].z), fabsf(v[i].w))));
    }
    #pragma unroll
    for (int off = 16; off > 0; off >>= 1) {
        s += __shfl_xor_sync(0xFFFFFFFFu, s, off);
        mx = fmaxf(mx, __shfl_xor_sync(0xFFFFFFFFu, mx, off));
    }
    mx = fmaxf(mx, 1e-20f);
    float sx = 127.f / mx;
    uint32_t* dst = reinterpret_cast<uint32_t*>((is_x ? g_xq : g_wq) + (size_t)row * K_IN);
    #pragma unroll
    for (int i = 0; i < 4; i++)
        dst[lane + i * 32] = pack4(v[i].x, v[i].y, v[i].z, v[i].w, sx);
    if (lane == 0) {
        if (is_x) g_dx[row] = mx / 127.f;
        else { g_w2[row] = s; g_dw[row] = mx / 127.f; }
    }
}

// ---------------- coarse GEMM (int8, 8 warps) with per-4col group-min epilogue ----------------
__global__ void __launch_bounds__(THREADS, 1)
gemm_coarse_kernel(int rowtile_base) {
    extern __shared__ char smem[];
    __shared__ float w2s[BN];
    __shared__ float dws[BN];
    __shared__ float dxs[BM];
    const uint32_t sb = smem_u32(smem);
    const int tid = threadIdx.x;
    const int row0 = (rowtile_base + blockIdx.x) * BM;
    const int col0 = blockIdx.y * BN;

    for (int i = tid; i < BN; i += THREADS) { w2s[i] = g_w2[col0 + i]; dws[i] = g_dw[col0 + i]; }
    if (tid < BM) dxs[tid] = g_dx[row0 + tid];

    const int lane = tid & 31, wid = tid >> 5;
    const int wm = wid >> 2, wn = wid & 3;   // 2 (M) x 4 (N) warps; warp tile 64x64

    // prologue: prefetch ALL 4 stages (one commit each)
    #pragma unroll
    for (int kc = 0; kc < NCHUNK; kc++) {
        uint32_t As = sb + kc * STAGE_BYTES;
        uint32_t Bs = As + A_ST_BYTES;
        const int8_t* gA = g_xq + (size_t)row0 * K_IN + kc * BK;
        const int8_t* gB = g_wq + (size_t)col0 * K_IN + kc * BK;
        #pragma unroll
        for (int i = 0; i < 4; i++) {
            int id = tid + i * THREADS;
            int r = id >> 3, c = id & 7;
            cp_async16(As + r * 128 + ((c ^ (r & 7)) * 16), gA + (size_t)r * K_IN + c * 16);
        }
        #pragma unroll
        for (int i = 0; i < 8; i++) {
            int id = tid + i * THREADS;
            int r = id >> 3, c = id & 7;
            cp_async16(Bs + r * 128 + ((c ^ (r & 7)) * 16), gB + (size_t)r * K_IN + c * 16);
        }
        cp_commit();
    }

    int acc[4][8][4];
    #pragma unroll
    for (int i = 0; i < 4; i++)
        #pragma unroll
        for (int j = 0; j < 8; j++)
            #pragma unroll
            for (int c = 0; c < 4; c++) acc[i][j][c] = 0;

    for (int ki = 0; ki < NCHUNK; ki++) {
        switch (ki) {
            case 0: cp_wait<3>(); break;
            case 1: cp_wait<2>(); break;
            case 2: cp_wait<1>(); break;
            default: cp_wait<0>(); break;
        }
        __syncthreads();
        uint32_t As = sb + ki * STAGE_BYTES;
        uint32_t Bs = As + A_ST_BYTES;

        #pragma unroll
        for (int kk = 0; kk < 4; kk++) {        // 4 x k32 per 128B chunk
            uint32_t afr[4][4];
            #pragma unroll
            for (int mi = 0; mi < 4; mi++) {
                int row = wm * 64 + mi * 16 + (lane & 15);
                int kc = kk * 2 + (lane >> 4);
                ldsm_x4(afr[mi], As + row * 128 + ((kc ^ (row & 7)) * 16));
            }
            uint32_t bfr[8][2];
            #pragma unroll
            for (int p = 0; p < 4; p++) {
                int n  = wn * 64 + p * 16 + (lane >> 4) * 8 + (lane & 7);
                int kc = kk * 2 + ((lane >> 3) & 1);
                uint32_t r[4];
                ldsm_x4(r, Bs + n * 128 + ((kc ^ (n & 7)) * 16));
                bfr[2 * p][0] = r[0]; bfr[2 * p][1] = r[1];
                bfr[2 * p + 1][0] = r[2]; bfr[2 * p + 1][1] = r[3];
            }
            #pragma unroll
            for (int mi = 0; mi < 4; mi++)
                #pragma unroll
                for (int nj = 0; nj < 8; nj++)
                    mma16832s8(acc[mi][nj], afr[mi], bfr[nj]);
        }
    }

    // ---- epilogue: score = w2 - 2*dx*dw*dot; reduce to per-4col group min ----
    const int qr = lane >> 2, qc = lane & 3;
    #pragma unroll
    for (int mi = 0; mi < 4; mi++) {
        #pragma unroll
        for (int h = 0; h < 2; h++) {
            int lrow = wm * 64 + mi * 16 + qr + h * 8;
            float ndx2 = -2.f * dxs[lrow];
            __half gm[8];
            #pragma unroll
            for (int nj = 0; nj < 8; nj++) {
                int cl = wn * 64 + nj * 8 + 2 * qc;
                float s0 = fmaf(ndx2 * dws[cl],     (float)acc[mi][nj][h * 2 + 0], w2s[cl]);
                float s1 = fmaf(ndx2 * dws[cl + 1], (float)acc[mi][nj][h * 2 + 1], w2s[cl + 1]);
                float m = fminf(s0, s1);
                m = fminf(m, __shfl_xor_sync(0xFFFFFFFFu, m, 1));   // min over qc pair
                gm[nj] = __float2half(m);
            }
            if ((qc & 1) == 0) {   // lanes qc=0 (p=0) and qc=2 (p=1) hold group minima
                uint4 v;
                __half2 p0 = __halves2half2(gm[0], gm[1]);
                __half2 p1 = __halves2half2(gm[2], gm[3]);
                __half2 p2 = __halves2half2(gm[4], gm[5]);
                __half2 p3 = __halves2half2(gm[6], gm[7]);
                v.x = *reinterpret_cast<uint32_t*>(&p0);
                v.y = *reinterpret_cast<uint32_t*>(&p1);
                v.z = *reinterpret_cast<uint32_t*>(&p2);
                v.w = *reinterpret_cast<uint32_t*>(&p3);
                *reinterpret_cast<uint4*>(
                    g_gmin + (size_t)(row0 + lrow) * NGRP
                           + blockIdx.y * 64 + wn * 16 + (qc >> 1) * 8) = v;
            }
        }
    }
}

// ---------------- fused refine + gather: block-per-row ----------------
__global__ void __launch_bounds__(256)
refine_gather_kernel(const float* __restrict__ X, const float* __restrict__ W,
                     const float* __restrict__ G, float* __restrict__ out,
                     int out_size, int row_base) {
    __shared__ float s_min[8];
    __shared__ short s_cand[CAP];
    __shared__ int s_cnt;
    __shared__ unsigned long long s_best;
    const int b = row_base + blockIdx.x, tid = threadIdx.x;
    const int lane = tid & 31, wid = tid >> 5;

    // pass 1: read this row's 4096 group minima (8 KB), block-min
    const uint4* gm4 = reinterpret_cast<const uint4*>(g_gmin + (size_t)b * NGRP);
    uint4 q0 = gm4[2 * tid], q1 = gm4[2 * tid + 1];
    __half2 hm = __hmin2(*reinterpret_cast<__half2*>(&q0.x),
                         *reinterpret_cast<__half2*>(&q0.y));
    hm = __hmin2(hm, __hmin2(*reinterpret_cast<__half2*>(&q0.z),
                             *reinterpret_cast<__half2*>(&q0.w)));
    hm = __hmin2(hm, __hmin2(*reinterpret_cast<__half2*>(&q1.x),
                             *reinterpret_cast<__half2*>(&q1.y)));
    hm = __hmin2(hm, __hmin2(*reinterpret_cast<__half2*>(&q1.z),
                             *reinterpret_cast<__half2*>(&q1.w)));
    float mn = fminf(__half2float(__low2half(hm)), __half2float(__high2half(hm)));
    #pragma unroll
    for (int o = 16; o > 0; o >>= 1) mn = fminf(mn, __shfl_xor_sync(0xFFFFFFFFu, mn, o));
    if (lane == 0) s_min[wid] = mn;
    if (tid == 0) { s_cnt = 0; s_best = ~0ULL; }
    __syncthreads();
    if (tid == 0) {
        float m = s_min[0];
        #pragma unroll
        for (int i = 1; i < 8; i++) m = fminf(m, s_min[i]);
        s_min[0] = m;
    }
    __syncthreads();
    const float thr = s_min[0] + MARGIN;

    // collect qualifying groups (thread owns storage half-indices 16*tid .. +15)
    {
        const __half* h0 = reinterpret_cast<const __half*>(&q0);
        const __half* h1 = reinterpret_cast<const __half*>(&q1);
        #pragma unroll
        for (int e = 0; e < 8; e++) {
            if (__half2float(h0[e]) <= thr) {
                int p = atomicAdd(&s_cnt, 1);
                if (p < CAP) s_cand[p] = (short)(16 * tid + e);
            }
            if (__half2float(h1[e]) <= thr) {
                int p = atomicAdd(&s_cnt, 1);
                if (p < CAP) s_cand[p] = (short)(16 * tid + 8 + e);
            }
        }
    }
    __syncthreads();
    const int cnt = min(s_cnt, CAP);

    // exact fp32 re-score: one warp per candidate column (4 cols per group)
    const float4* x4 = reinterpret_cast<const float4*>(X + (size_t)b * K_IN);
    for (int item = wid; item < cnt * 4; item += 8) {
        int j = group_colbase((int)s_cand[item >> 2]) + (item & 3);
        const float4* w4 = reinterpret_cast<const float4*>(W + (size_t)j * K_IN);
        float acc = 0.f;
        #pragma unroll
        for (int i = 0; i < 4; i++) {
            float4 a = x4[lane + i * 32], w = w4[lane + i * 32];
            acc += a.x * w.x + a.y * w.y + a.z * w.z + a.w * w.w;
        }
        #pragma unroll
        for (int o = 16; o > 0; o >>= 1) acc += __shfl_xor_sync(0xFFFFFFFFu, acc, o);
        if (lane == 0) {
            float s = fmaf(-2.f, acc, g_w2[j]);
            unsigned long long p =
                ((unsigned long long)f32_key(s) << 32) | (unsigned int)j;
            atomicMin(&s_best, p);
        }
    }
    __syncthreads();

    // gather grossberg column of the winner
    unsigned int w = (unsigned int)(s_best & 0xFFFFFFFFull);
    for (int o = tid; o < N_OUT; o += 256)
        out[(size_t)b * N_OUT + o] = G[(size_t)o * H_HID + w];
    if (tid == 0 && out_size >= B_BATCH * N_OUT + B_BATCH)
        out[(size_t)B_BATCH * N_OUT + b] = (float)w;
}

// ---------------- launcher: fork-join overlap of refine chunks with GEMM chunks ----------------
extern "C" void kernel_launch(void* const* d_in, const int* in_sizes, int n_in,
                              void* d_out, int out_size) {
    const float* x  = (const float*)d_in[0];   // [4096, 512]
    const float* kw = (const float*)d_in[1];   // [16384, 512]
    const float* gw = (const float*)d_in[2];   // [1000, 16384]
    float* out = (float*)d_out;

    cudaFuncSetAttribute(gemm_coarse_kernel,
                         cudaFuncAttributeMaxDynamicSharedMemorySize, GEMM_SMEM);

    prep_kernel<<<(B_BATCH + H_HID) / 8, 256>>>(x, kw);

    const bool ov = g_res.ok;
    for (int c = 0; c < NSPLIT; c++) {
        dim3 grid(RT_PER, H_HID / BN);   // (8, 64) per chunk
        gemm_coarse_kernel<<<grid, THREADS, GEMM_SMEM>>>(c * RT_PER);
        if (ov) {
            cudaEventRecord(g_res.evFork[c], (cudaStream_t)0);
            cudaStreamWaitEvent(g_res.s2, g_res.evFork[c], 0);
            refine_gather_kernel<<<RT_PER * BM, 256, 0, g_res.s2>>>(
                x, kw, gw, out, out_size, c * RT_PER * BM);
        }
    }
    if (ov) {
        cudaEventRecord(g_res.evJoin, g_res.s2);
        cudaStreamWaitEvent((cudaStream_t)0, g_res.evJoin, 0);
    } else {
        refine_gather_kernel<<<B_BATCH, 256>>>(x, kw, gw, out, out_size, 0);
    }
}

// round 15
// speedup vs baseline: 1.1196x; 1.1196x over previous
#include <cuda_runtime.h>
#include <cuda_fp16.h>
#include <cstdint>

// Problem constants: BATCH=4096, IN=512, HID=16384, OUT=1000
#define B_BATCH 4096
#define K_IN    512
#define H_HID   16384
#define N_OUT   1000

// Coarse GEMM tiling (int8): CTA 128x256, warp tile 64x64, 8 warps (proven config)
#define BM 128
#define BN 256
#define BK 128
#define STAGES 4
#define THREADS 256
#define NCHUNK (K_IN / BK)   // 4 == STAGES: full prefetch

#define A_ST_BYTES (BM * BK)                  // 16384
#define B_ST_BYTES (BN * BK)                  // 32768
#define STAGE_BYTES (A_ST_BYTES + B_ST_BYTES) // 49152
#define GEMM_SMEM (STAGES * STAGE_BYTES)      // 196608

#define NGRP (H_HID / 4)     // 4096 groups of 4 columns per batch row
#define MARGIN 0.5f
#define CAP 1024

#define NSPLIT 2             // row-chunks for GEMM/refine overlap (1024 CTAs each)
#define RT_PER (32 / NSPLIT) // 16 row-tiles per chunk

// ---------------- device scratch (static; no allocs) ----------------
__device__ int8_t g_xq[(size_t)B_BATCH * K_IN];            // 2 MB
__device__ int8_t g_wq[(size_t)H_HID * K_IN];              // 8 MB
__device__ float  g_dx[B_BATCH];
__device__ float  g_dw[H_HID];
__device__ __half g_gmin[(size_t)B_BATCH * NGRP];          // 32 MB: per-4col group minima
__device__ float  g_w2[H_HID];

// ---------------- overlap resources (created once at static init; host-side) ----------------
struct OverlapRes {
    cudaStream_t s2 = nullptr;
    cudaEvent_t  evFork[NSPLIT] = {};
    cudaEvent_t  evJoin = nullptr;
    bool ok = false;
    OverlapRes() {
        if (cudaStreamCreateWithFlags(&s2, cudaStreamNonBlocking) != cudaSuccess) return;
        for (int i = 0; i < NSPLIT; i++)
            if (cudaEventCreateWithFlags(&evFork[i], cudaEventDisableTiming) != cudaSuccess)
                return;
        if (cudaEventCreateWithFlags(&evJoin, cudaEventDisableTiming) != cudaSuccess) return;
        ok = true;
    }
};
static OverlapRes g_res;

// ---------------- helpers ----------------
__device__ __forceinline__ uint32_t smem_u32(const void* p) {
    uint32_t a;
    asm("{ .reg .u64 t; cvta.to.shared.u64 t, %1; cvt.u32.u64 %0, t; }" : "=r"(a) : "l"(p));
    return a;
}
__device__ __forceinline__ void cp_async16(uint32_t dst, const void* src) {
    asm volatile("cp.async.cg.shared.global [%0], [%1], 16;" :: "r"(dst), "l"(src) : "memory");
}
__device__ __forceinline__ void cp_commit() {
    asm volatile("cp.async.commit_group;" ::: "memory");
}
template <int N>
__device__ __forceinline__ void cp_wait() {
    asm volatile("cp.async.wait_group %0;" :: "n"(N) : "memory");
}
__device__ __forceinline__ void ldsm_x4(uint32_t* r, uint32_t addr) {
    asm volatile("ldmatrix.sync.aligned.m8n8.x4.shared.b16 {%0,%1,%2,%3}, [%4];"
                 : "=r"(r[0]), "=r"(r[1]), "=r"(r[2]), "=r"(r[3]) : "r"(addr));
}
__device__ __forceinline__ void mma16832s8(int* c, const uint32_t* a, const uint32_t* b) {
    asm volatile(
        "mma.sync.aligned.m16n8k32.row.col.s32.s8.s8.s32 "
        "{%0,%1,%2,%3}, {%4,%5,%6,%7}, {%8,%9}, {%0,%1,%2,%3};"
        : "+r"(c[0]), "+r"(c[1]), "+r"(c[2]), "+r"(c[3])
        : "r"(a[0]), "r"(a[1]), "r"(a[2]), "r"(a[3]), "r"(b[0]), "r"(b[1]));
}
__device__ __forceinline__ unsigned int f32_key(float f) {
    unsigned int u = __float_as_uint(f);
    return u ^ ((u & 0x80000000u) ? 0xFFFFFFFFu : 0x80000000u);
}
__device__ __forceinline__ uint32_t pack4(float a, float b, float c, float d, float sx) {
    int ia = __float2int_rn(fminf(fmaxf(a * sx, -127.f), 127.f));
    int ib = __float2int_rn(fminf(fmaxf(b * sx, -127.f), 127.f));
    int ic = __float2int_rn(fminf(fmaxf(c * sx, -127.f), 127.f));
    int id = __float2int_rn(fminf(fmaxf(d * sx, -127.f), 127.f));
    return (ia & 0xFF) | ((ib & 0xFF) << 8) | ((ic & 0xFF) << 16) | ((id & 0xFF) << 24);
}
// storage half-index -> base column of its 4-col group (epilogue packing inverse)
__device__ __forceinline__ int group_colbase(int hidx) {
    int tile = hidx >> 6, t = hidx & 63;
    int wn = t >> 4, r = t & 15;
    int p = r >> 3, nj = r & 7;
    return tile * 256 + wn * 64 + nj * 8 + p * 4;
}

// ---------------- prep (merged): int8 quantize X and W rows (+ exact w2 for W) ----------------
__global__ void prep_kernel(const float* __restrict__ X, const float* __restrict__ W) {
    int warp = threadIdx.x >> 5, lane = threadIdx.x & 31;
    bool is_x = blockIdx.x < (B_BATCH / 8);
    int row = (is_x ? blockIdx.x : blockIdx.x - B_BATCH / 8) * 8 + warp;
    const float* src = is_x ? X : W;
    const float4* p = reinterpret_cast<const float4*>(src + (size_t)row * K_IN);
    float4 v[4];
    float s = 0.f, mx = 0.f;
    #pragma unroll
    for (int i = 0; i < 4; i++) {
        v[i] = p[lane + i * 32];
        s += v[i].x * v[i].x + v[i].y * v[i].y + v[i].z * v[i].z + v[i].w * v[i].w;
        mx = fmaxf(mx, fmaxf(fmaxf(fabsf(v[i].x), fabsf(v[i].y)),
                             fmaxf(fabsf(v[i].z), fabsf(v[i].w))));
    }
    #pragma unroll
    for (int off = 16; off > 0; off >>= 1) {
        s += __shfl_xor_sync(0xFFFFFFFFu, s, off);
        mx = fmaxf(mx, __shfl_xor_sync(0xFFFFFFFFu, mx, off));
    }
    mx = fmaxf(mx, 1e-20f);
    float sx = 127.f / mx;
    uint32_t* dst = reinterpret_cast<uint32_t*>((is_x ? g_xq : g_wq) + (size_t)row * K_IN);
    #pragma unroll
    for (int i = 0; i < 4; i++)
        dst[lane + i * 32] = pack4(v[i].x, v[i].y, v[i].z, v[i].w, sx);
    if (lane == 0) {
        if (is_x) g_dx[row] = mx / 127.f;
        else { g_w2[row] = s; g_dw[row] = mx / 127.f; }
    }
}

// ---------------- coarse GEMM (int8, 8 warps) with per-4col group-min epilogue ----------------
__global__ void __launch_bounds__(THREADS, 1)
gemm_coarse_kernel(int rowtile_base) {
    extern __shared__ char smem[];
    __shared__ float w2s[BN];
    __shared__ float dws[BN];
    __shared__ float dxs[BM];
    const uint32_t sb = smem_u32(smem);
    const int tid = threadIdx.x;
    const int row0 = (rowtile_base + blockIdx.x) * BM;
    const int col0 = blockIdx.y * BN;

    for (int i = tid; i < BN; i += THREADS) { w2s[i] = g_w2[col0 + i]; dws[i] = g_dw[col0 + i]; }
    if (tid < BM) dxs[tid] = g_dx[row0 + tid];

    const int lane = tid & 31, wid = tid >> 5;
    const int wm = wid >> 2, wn = wid & 3;   // 2 (M) x 4 (N) warps; warp tile 64x64

    // prologue: prefetch ALL 4 stages (one commit each)
    #pragma unroll
    for (int kc = 0; kc < NCHUNK; kc++) {
        uint32_t As = sb + kc * STAGE_BYTES;
        uint32_t Bs = As + A_ST_BYTES;
        const int8_t* gA = g_xq + (size_t)row0 * K_IN + kc * BK;
        const int8_t* gB = g_wq + (size_t)col0 * K_IN + kc * BK;
        #pragma unroll
        for (int i = 0; i < 4; i++) {
            int id = tid + i * THREADS;
            int r = id >> 3, c = id & 7;
            cp_async16(As + r * 128 + ((c ^ (r & 7)) * 16), gA + (size_t)r * K_IN + c * 16);
        }
        #pragma unroll
        for (int i = 0; i < 8; i++) {
            int id = tid + i * THREADS;
            int r = id >> 3, c = id & 7;
            cp_async16(Bs + r * 128 + ((c ^ (r & 7)) * 16), gB + (size_t)r * K_IN + c * 16);
        }
        cp_commit();
    }

    int acc[4][8][4];
    #pragma unroll
    for (int i = 0; i < 4; i++)
        #pragma unroll
        for (int j = 0; j < 8; j++)
            #pragma unroll
            for (int c = 0; c < 4; c++) acc[i][j][c] = 0;

    for (int ki = 0; ki < NCHUNK; ki++) {
        switch (ki) {
            case 0: cp_wait<3>(); break;
            case 1: cp_wait<2>(); break;
            case 2: cp_wait<1>(); break;
            default: cp_wait<0>(); break;
        }
        __syncthreads();
        uint32_t As = sb + ki * STAGE_BYTES;
        uint32_t Bs = As + A_ST_BYTES;

        #pragma unroll
        for (int kk = 0; kk < 4; kk++) {        // 4 x k32 per 128B chunk
            uint32_t afr[4][4];
            #pragma unroll
            for (int mi = 0; mi < 4; mi++) {
                int row = wm * 64 + mi * 16 + (lane & 15);
                int kc = kk * 2 + (lane >> 4);
                ldsm_x4(afr[mi], As + row * 128 + ((kc ^ (row & 7)) * 16));
            }
            uint32_t bfr[8][2];
            #pragma unroll
            for (int p = 0; p < 4; p++) {
                int n  = wn * 64 + p * 16 + (lane >> 4) * 8 + (lane & 7);
                int kc = kk * 2 + ((lane >> 3) & 1);
                uint32_t r[4];
                ldsm_x4(r, Bs + n * 128 + ((kc ^ (n & 7)) * 16));
                bfr[2 * p][0] = r[0]; bfr[2 * p][1] = r[1];
                bfr[2 * p + 1][0] = r[2]; bfr[2 * p + 1][1] = r[3];
            }
            #pragma unroll
            for (int mi = 0; mi < 4; mi++)
                #pragma unroll
                for (int nj = 0; nj < 8; nj++)
                    mma16832s8(acc[mi][nj], afr[mi], bfr[nj]);
        }
    }

    // ---- epilogue: score = w2 - 2*dx*dw*dot; reduce to per-4col group min ----
    const int qr = lane >> 2, qc = lane & 3;
    #pragma unroll
    for (int mi = 0; mi < 4; mi++) {
        #pragma unroll
        for (int h = 0; h < 2; h++) {
            int lrow = wm * 64 + mi * 16 + qr + h * 8;
            float ndx2 = -2.f * dxs[lrow];
            __half gm[8];
            #pragma unroll
            for (int nj = 0; nj < 8; nj++) {
                int cl = wn * 64 + nj * 8 + 2 * qc;
                float s0 = fmaf(ndx2 * dws[cl],     (float)acc[mi][nj][h * 2 + 0], w2s[cl]);
                float s1 = fmaf(ndx2 * dws[cl + 1], (float)acc[mi][nj][h * 2 + 1], w2s[cl + 1]);
                float m = fminf(s0, s1);
                m = fminf(m, __shfl_xor_sync(0xFFFFFFFFu, m, 1));   // min over qc pair
                gm[nj] = __float2half(m);
            }
            if ((qc & 1) == 0) {   // lanes qc=0 (p=0) and qc=2 (p=1) hold group minima
                uint4 v;
                __half2 p0 = __halves2half2(gm[0], gm[1]);
                __half2 p1 = __halves2half2(gm[2], gm[3]);
                __half2 p2 = __halves2half2(gm[4], gm[5]);
                __half2 p3 = __halves2half2(gm[6], gm[7]);
                v.x = *reinterpret_cast<uint32_t*>(&p0);
                v.y = *reinterpret_cast<uint32_t*>(&p1);
                v.z = *reinterpret_cast<uint32_t*>(&p2);
                v.w = *reinterpret_cast<uint32_t*>(&p3);
                *reinterpret_cast<uint4*>(
                    g_gmin + (size_t)(row0 + lrow) * NGRP
                           + blockIdx.y * 64 + wn * 16 + (qc >> 1) * 8) = v;
            }
        }
    }
}

// ---------------- fused refine + gather: block-per-row ----------------
__global__ void __launch_bounds__(256)
refine_gather_kernel(const float* __restrict__ X, const float* __restrict__ W,
                     const float* __restrict__ G, float* __restrict__ out,
                     int out_size, int row_base) {
    __shared__ float s_min[8];
    __shared__ short s_cand[CAP];
    __shared__ int s_cnt;
    __shared__ unsigned long long s_best;
    const int b = row_base + blockIdx.x, tid = threadIdx.x;
    const int lane = tid & 31, wid = tid >> 5;

    // pass 1: read this row's 4096 group minima (8 KB), block-min
    const uint4* gm4 = reinterpret_cast<const uint4*>(g_gmin + (size_t)b * NGRP);
    uint4 q0 = gm4[2 * tid], q1 = gm4[2 * tid + 1];
    __half2 hm = __hmin2(*reinterpret_cast<__half2*>(&q0.x),
                         *reinterpret_cast<__half2*>(&q0.y));
    hm = __hmin2(hm, __hmin2(*reinterpret_cast<__half2*>(&q0.z),
                             *reinterpret_cast<__half2*>(&q0.w)));
    hm = __hmin2(hm, __hmin2(*reinterpret_cast<__half2*>(&q1.x),
                             *reinterpret_cast<__half2*>(&q1.y)));
    hm = __hmin2(hm, __hmin2(*reinterpret_cast<__half2*>(&q1.z),
                             *reinterpret_cast<__half2*>(&q1.w)));
    float mn = fminf(__half2float(__low2half(hm)), __half2float(__high2half(hm)));
    #pragma unroll
    for (int o = 16; o > 0; o >>= 1) mn = fminf(mn, __shfl_xor_sync(0xFFFFFFFFu, mn, o));
    if (lane == 0) s_min[wid] = mn;
    if (tid == 0) { s_cnt = 0; s_best = ~0ULL; }
    __syncthreads();
    if (tid == 0) {
        float m = s_min[0];
        #pragma unroll
        for (int i = 1; i < 8; i++) m = fminf(m, s_min[i]);
        s_min[0] = m;
    }
    __syncthreads();
    const float thr = s_min[0] + MARGIN;

    // collect qualifying groups (thread owns storage half-indices 16*tid .. +15)
    {
        const __half* h0 = reinterpret_cast<const __half*>(&q0);
        const __half* h1 = reinterpret_cast<const __half*>(&q1);
        #pragma unroll
        for (int e = 0; e < 8; e++) {
            if (__half2float(h0[e]) <= thr) {
                int p = atomicAdd(&s_cnt, 1);
                if (p < CAP) s_cand[p] = (short)(16 * tid + e);
            }
            if (__half2float(h1[e]) <= thr) {
                int p = atomicAdd(&s_cnt, 1);
                if (p < CAP) s_cand[p] = (short)(16 * tid + 8 + e);
            }
        }
    }
    __syncthreads();
    const int cnt = min(s_cnt, CAP);

    // exact fp32 re-score: one warp per candidate column (4 cols per group)
    const float4* x4 = reinterpret_cast<const float4*>(X + (size_t)b * K_IN);
    for (int item = wid; item < cnt * 4; item += 8) {
        int j = group_colbase((int)s_cand[item >> 2]) + (item & 3);
        const float4* w4 = reinterpret_cast<const float4*>(W + (size_t)j * K_IN);
        float acc = 0.f;
        #pragma unroll
        for (int i = 0; i < 4; i++) {
            float4 a = x4[lane + i * 32], w = w4[lane + i * 32];
            acc += a.x * w.x + a.y * w.y + a.z * w.z + a.w * w.w;
        }
        #pragma unroll
        for (int o = 16; o > 0; o >>= 1) acc += __shfl_xor_sync(0xFFFFFFFFu, acc, o);
        if (lane == 0) {
            float s = fmaf(-2.f, acc, g_w2[j]);
            unsigned long long p =
                ((unsigned long long)f32_key(s) << 32) | (unsigned int)j;
            atomicMin(&s_best, p);
        }
    }
    __syncthreads();

    // gather grossberg column of the winner
    unsigned int w = (unsigned int)(s_best & 0xFFFFFFFFull);
    for (int o = tid; o < N_OUT; o += 256)
        out[(size_t)b * N_OUT + o] = G[(size_t)o * H_HID + w];
    if (tid == 0 && out_size >= B_BATCH * N_OUT + B_BATCH)
        out[(size_t)B_BATCH * N_OUT + b] = (float)w;
}

// ---------------- launcher: 2-way fork-join overlap ----------------
extern "C" void kernel_launch(void* const* d_in, const int* in_sizes, int n_in,
                              void* d_out, int out_size) {
    const float* x  = (const float*)d_in[0];   // [4096, 512]
    const float* kw = (const float*)d_in[1];   // [16384, 512]
    const float* gw = (const float*)d_in[2];   // [1000, 16384]
    float* out = (float*)d_out;

    cudaFuncSetAttribute(gemm_coarse_kernel,
                         cudaFuncAttributeMaxDynamicSharedMemorySize, GEMM_SMEM);

    prep_kernel<<<(B_BATCH + H_HID) / 8, 256>>>(x, kw);

    const bool ov = g_res.ok;
    if (ov) {
        for (int c = 0; c < NSPLIT; c++) {
            dim3 grid(RT_PER, H_HID / BN);   // (16, 64) per chunk: 1024 CTAs
            gemm_coarse_kernel<<<grid, THREADS, GEMM_SMEM>>>(c * RT_PER);
            cudaEventRecord(g_res.evFork[c], (cudaStream_t)0);
            cudaStreamWaitEvent(g_res.s2, g_res.evFork[c], 0);
            refine_gather_kernel<<<RT_PER * BM, 256, 0, g_res.s2>>>(
                x, kw, gw, out, out_size, c * RT_PER * BM);
        }
        cudaEventRecord(g_res.evJoin, g_res.s2);
        cudaStreamWaitEvent((cudaStream_t)0, g_res.evJoin, 0);
    } else {
        dim3 grid(32, H_HID / BN);
        gemm_coarse_kernel<<<grid, THREADS, GEMM_SMEM>>>(0);
        refine_gather_kernel<<<B_BATCH, 256>>>(x, kw, gw, out, out_size, 0);
    }
}

// round 17
// speedup vs baseline: 1.3224x; 1.1811x over previous
#include <cuda_runtime.h>
#include <cuda_fp16.h>
#include <cstdint>

// Problem constants: BATCH=4096, IN=512, HID=16384, OUT=1000
#define B_BATCH 4096
#define K_IN    512
#define H_HID   16384
#define N_OUT   1000

// Coarse GEMM tiling (int8): CTA 128x128, warp tile 64x32, 8 warps, 2 CTAs/SM
#define BM 128
#define BN 128
#define BK 128
#define STAGES 3
#define THREADS 256
#define NCHUNK (K_IN / BK)   // 4

#define A_ST_BYTES (BM * BK)                  // 16384
#define B_ST_BYTES (BN * BK)                  // 16384
#define STAGE_BYTES (A_ST_BYTES + B_ST_BYTES) // 32768
#define GEMM_SMEM (STAGES * STAGE_BYTES)      // 98304 (2 CTAs/SM: 196KB < 227KB)

#define NGRP (H_HID / 4)     // 4096 groups of 4 columns per batch row
#define MARGIN 0.5f
#define CAP 1024

// ---------------- device scratch (static; no allocs) ----------------
__device__ int8_t g_xq[(size_t)B_BATCH * K_IN];            // 2 MB
__device__ int8_t g_wq[(size_t)H_HID * K_IN];              // 8 MB
__device__ float  g_dx[B_BATCH];
__device__ float  g_dw[H_HID];
__device__ __half g_gmin[(size_t)B_BATCH * NGRP];          // 32 MB: per-4col group minima
__device__ float  g_w2[H_HID];

// ---------------- helpers ----------------
__device__ __forceinline__ uint32_t smem_u32(const void* p) {
    uint32_t a;
    asm("{ .reg .u64 t; cvta.to.shared.u64 t, %1; cvt.u32.u64 %0, t; }" : "=r"(a) : "l"(p));
    return a;
}
__device__ __forceinline__ void cp_async16(uint32_t dst, const void* src) {
    asm volatile("cp.async.cg.shared.global [%0], [%1], 16;" :: "r"(dst), "l"(src) : "memory");
}
__device__ __forceinline__ void cp_commit() {
    asm volatile("cp.async.commit_group;" ::: "memory");
}
__device__ __forceinline__ void cp_wait1() {
    asm volatile("cp.async.wait_group 1;" ::: "memory");
}
__device__ __forceinline__ void cp_wait0() {
    asm volatile("cp.async.wait_group 0;" ::: "memory");
}
__device__ __forceinline__ void ldsm_x4(uint32_t* r, uint32_t addr) {
    asm volatile("ldmatrix.sync.aligned.m8n8.x4.shared.b16 {%0,%1,%2,%3}, [%4];"
                 : "=r"(r[0]), "=r"(r[1]), "=r"(r[2]), "=r"(r[3]) : "r"(addr));
}
__device__ __forceinline__ void mma16832s8(int* c, const uint32_t* a, const uint32_t* b) {
    asm volatile(
        "mma.sync.aligned.m16n8k32.row.col.s32.s8.s8.s32 "
        "{%0,%1,%2,%3}, {%4,%5,%6,%7}, {%8,%9}, {%0,%1,%2,%3};"
        : "+r"(c[0]), "+r"(c[1]), "+r"(c[2]), "+r"(c[3])
        : "r"(a[0]), "r"(a[1]), "r"(a[2]), "r"(a[3]), "r"(b[0]), "r"(b[1]));
}
__device__ __forceinline__ unsigned int f32_key(float f) {
    unsigned int u = __float_as_uint(f);
    return u ^ ((u & 0x80000000u) ? 0xFFFFFFFFu : 0x80000000u);
}
__device__ __forceinline__ uint32_t pack4(float a, float b, float c, float d, float sx) {
    int ia = __float2int_rn(fminf(fmaxf(a * sx, -127.f), 127.f));
    int ib = __float2int_rn(fminf(fmaxf(b * sx, -127.f), 127.f));
    int ic = __float2int_rn(fminf(fmaxf(c * sx, -127.f), 127.f));
    int id = __float2int_rn(fminf(fmaxf(d * sx, -127.f), 127.f));
    return (ia & 0xFF) | ((ib & 0xFF) << 8) | ((ic & 0xFF) << 16) | ((id & 0xFF) << 24);
}
// storage half-index -> base column of its 4-col group (BN=128 epilogue packing inverse)
// per 128-col tile: 32 slots = wn(4) * 8 + p(2) * 4 + nj(4)
__device__ __forceinline__ int group_colbase(int hidx) {
    int tile = hidx >> 5, t = hidx & 31;
    int wn = t >> 3, r = t & 7;
    int p = r >> 2, nj = r & 3;
    return tile * 128 + wn * 32 + nj * 8 + p * 4;
}

// ---------------- prep (merged): int8 quantize X and W rows (+ exact w2 for W) ----------------
__global__ void prep_kernel(const float* __restrict__ X, const float* __restrict__ W) {
    int warp = threadIdx.x >> 5, lane = threadIdx.x & 31;
    bool is_x = blockIdx.x < (B_BATCH / 8);
    int row = (is_x ? blockIdx.x : blockIdx.x - B_BATCH / 8) * 8 + warp;
    const float* src = is_x ? X : W;
    const float4* p = reinterpret_cast<const float4*>(src + (size_t)row * K_IN);
    float4 v[4];
    float s = 0.f, mx = 0.f;
    #pragma unroll
    for (int i = 0; i < 4; i++) {
        v[i] = p[lane + i * 32];
        s += v[i].x * v[i].x + v[i].y * v[i].y + v[i].z * v[i].z + v[i].w * v[i].w;
        mx = fmaxf(mx, fmaxf(fmaxf(fabsf(v[i].x), fabsf(v[i].y)),
                             fmaxf(fabsf(v[i].z), fabsf(v[i].w))));
    }
    #pragma unroll
    for (int off = 16; off > 0; off >>= 1) {
        s += __shfl_xor_sync(0xFFFFFFFFu, s, off);
        mx = fmaxf(mx, __shfl_xor_sync(0xFFFFFFFFu, mx, off));
    }
    mx = fmaxf(mx, 1e-20f);
    float sx = 127.f / mx;
    uint32_t* dst = reinterpret_cast<uint32_t*>((is_x ? g_xq : g_wq) + (size_t)row * K_IN);
    #pragma unroll
    for (int i = 0; i < 4; i++)
        dst[lane + i * 32] = pack4(v[i].x, v[i].y, v[i].z, v[i].w, sx);
    if (lane == 0) {
        if (is_x) g_dx[row] = mx / 127.f;
        else { g_w2[row] = s; g_dw[row] = mx / 127.f; }
    }
}

// ---------------- coarse GEMM (int8, 128x128, 2 CTAs/SM) with per-4col group-min epilogue ----------------
__global__ void __launch_bounds__(THREADS, 2)
gemm_coarse_kernel() {
    extern __shared__ char smem[];
    __shared__ float w2s[BN];
    __shared__ float dws[BN];
    __shared__ float dxs[BM];
    const uint32_t sb = smem_u32(smem);
    const int tid = threadIdx.x;
    const int row0 = blockIdx.x * BM;
    const int col0 = blockIdx.y * BN;

    if (tid < BN) { w2s[tid] = g_w2[col0 + tid]; dws[tid] = g_dw[col0 + tid]; }
    if (tid < BM) dxs[tid] = g_dx[row0 + tid];

    const int lane = tid & 31, wid = tid >> 5;
    const int wm = wid >> 2, wn = wid & 3;   // 2 (M) x 4 (N) warps; warp tile 64x32

    auto issue_stage = [&](int kc, int s) {
        uint32_t As = sb + s * STAGE_BYTES;
        uint32_t Bs = As + A_ST_BYTES;
        const int8_t* gA = g_xq + (size_t)row0 * K_IN + kc * BK;
        const int8_t* gB = g_wq + (size_t)col0 * K_IN + kc * BK;
        #pragma unroll
        for (int i = 0; i < 4; i++) {           // A: 128 rows x 8 chunks of 16B
            int id = tid + i * THREADS;
            int r = id >> 3, c = id & 7;
            cp_async16(As + r * 128 + ((c ^ (r & 7)) * 16), gA + (size_t)r * K_IN + c * 16);
        }
        #pragma unroll
        for (int i = 0; i < 4; i++) {           // B: 128 rows x 8 chunks of 16B
            int id = tid + i * THREADS;
            int r = id >> 3, c = id & 7;
            cp_async16(Bs + r * 128 + ((c ^ (r & 7)) * 16), gB + (size_t)r * K_IN + c * 16);
        }
        cp_commit();
    };

    int acc[4][4][4];
    #pragma unroll
    for (int i = 0; i < 4; i++)
        #pragma unroll
        for (int j = 0; j < 4; j++)
            #pragma unroll
            for (int c = 0; c < 4; c++) acc[i][j][c] = 0;

    issue_stage(0, 0);
    issue_stage(1, 1);

    for (int ki = 0; ki < NCHUNK; ki++) {
        if (ki == NCHUNK - 1) cp_wait0(); else cp_wait1();
        __syncthreads();
        if (ki + 2 < NCHUNK) issue_stage(ki + 2, (ki + 2) % STAGES);

        uint32_t As = sb + (ki % STAGES) * STAGE_BYTES;
        uint32_t Bs = As + A_ST_BYTES;

        #pragma unroll
        for (int kk = 0; kk < 4; kk++) {        // 4 x k32 per 128B chunk
            uint32_t afr[4][4];
            #pragma unroll
            for (int mi = 0; mi < 4; mi++) {
                int row = wm * 64 + mi * 16 + (lane & 15);
                int kc = kk * 2 + (lane >> 4);
                ldsm_x4(afr[mi], As + row * 128 + ((kc ^ (row & 7)) * 16));
            }
            uint32_t bfr[4][2];
            #pragma unroll
            for (int p = 0; p < 2; p++) {       // each x4 covers 2 n8-tiles
                int n  = wn * 32 + p * 16 + (lane >> 4) * 8 + (lane & 7);
                int kc = kk * 2 + ((lane >> 3) & 1);
                uint32_t r[4];
                ldsm_x4(r, Bs + n * 128 + ((kc ^ (n & 7)) * 16));
                bfr[2 * p][0] = r[0]; bfr[2 * p][1] = r[1];
                bfr[2 * p + 1][0] = r[2]; bfr[2 * p + 1][1] = r[3];
            }
            #pragma unroll
            for (int mi = 0; mi < 4; mi++)
                #pragma unroll
                for (int nj = 0; nj < 4; nj++)
                    mma16832s8(acc[mi][nj], afr[mi], bfr[nj]);
        }
    }

    // ---- epilogue: score = w2 - 2*dx*dw*dot; reduce to per-4col group min ----
    // storage (half index within row): blockIdx.y*32 + wn*8 + p*4 + nj, p = qc>>1
    const int qr = lane >> 2, qc = lane & 3;
    #pragma unroll
    for (int mi = 0; mi < 4; mi++) {
        #pragma unroll
        for (int h = 0; h < 2; h++) {
            int lrow = wm * 64 + mi * 16 + qr + h * 8;
            float ndx2 = -2.f * dxs[lrow];
            __half gm[4];
            #pragma unroll
            for (int nj = 0; nj < 4; nj++) {
                int cl = wn * 32 + nj * 8 + 2 * qc;
                float s0 = fmaf(ndx2 * dws[cl],     (float)acc[mi][nj][h * 2 + 0], w2s[cl]);
                float s1 = fmaf(ndx2 * dws[cl + 1], (float)acc[mi][nj][h * 2 + 1], w2s[cl + 1]);
                float m = fminf(s0, s1);
                m = fminf(m, __shfl_xor_sync(0xFFFFFFFFu, m, 1));   // min over qc pair
                gm[nj] = __float2half(m);
            }
            if ((qc & 1) == 0) {   // lanes qc=0 (p=0) and qc=2 (p=1) hold group minima
                uint2 v;
                __half2 p0 = __halves2half2(gm[0], gm[1]);
                __half2 p1 = __halves2half2(gm[2], gm[3]);
                v.x = *reinterpret_cast<uint32_t*>(&p0);
                v.y = *reinterpret_cast<uint32_t*>(&p1);
                *reinterpret_cast<uint2*>(
                    g_gmin + (size_t)(row0 + lrow) * NGRP
                           + blockIdx.y * 32 + wn * 8 + (qc >> 1) * 4) = v;
            }
        }
    }
}

// ---------------- fused refine + gather: block-per-row ----------------
__global__ void __launch_bounds__(256)
refine_gather_kernel(const float* __restrict__ X, const float* __restrict__ W,
                     const float* __restrict__ G, float* __restrict__ out,
                     int out_size) {
    __shared__ float s_min[8];
    __shared__ short s_cand[CAP];
    __shared__ int s_cnt;
    __shared__ unsigned long long s_best;
    const int b = blockIdx.x, tid = threadIdx.x;
    const int lane = tid & 31, wid = tid >> 5;

    // pass 1: read this row's 4096 group minima (8 KB), block-min
    const uint4* gm4 = reinterpret_cast<const uint4*>(g_gmin + (size_t)b * NGRP);
    uint4 q0 = gm4[2 * tid], q1 = gm4[2 * tid + 1];
    __half2 hm = __hmin2(*reinterpret_cast<__half2*>(&q0.x),
                         *reinterpret_cast<__half2*>(&q0.y));
    hm = __hmin2(hm, __hmin2(*reinterpret_cast<__half2*>(&q0.z),
                             *reinterpret_cast<__half2*>(&q0.w)));
    hm = __hmin2(hm, __hmin2(*reinterpret_cast<__half2*>(&q1.x),
                             *reinterpret_cast<__half2*>(&q1.y)));
    hm = __hmin2(hm, __hmin2(*reinterpret_cast<__half2*>(&q1.z),
                             *reinterpret_cast<__half2*>(&q1.w)));
    float mn = fminf(__half2float(__low2half(hm)), __half2float(__high2half(hm)));
    #pragma unroll
    for (int o = 16; o > 0; o >>= 1) mn = fminf(mn, __shfl_xor_sync(0xFFFFFFFFu, mn, o));
    if (lane == 0) s_min[wid] = mn;
    if (tid == 0) { s_cnt = 0; s_best = ~0ULL; }
    __syncthreads();
    if (tid == 0) {
        float m = s_min[0];
        #pragma unroll
        for (int i = 1; i < 8; i++) m = fminf(m, s_min[i]);
        s_min[0] = m;
    }
    __syncthreads();
    const float thr = s_min[0] + MARGIN;

    // collect qualifying groups (thread owns storage half-indices 16*tid .. +15)
    {
        const __half* h0 = reinterpret_cast<const __half*>(&q0);
        const __half* h1 = reinterpret_cast<const __half*>(&q1);
        #pragma unroll
        for (int e = 0; e < 8; e++) {
            if (__half2float(h0[e]) <= thr) {
                int p = atomicAdd(&s_cnt, 1);
                if (p < CAP) s_cand[p] = (short)(16 * tid + e);
            }
            if (__half2float(h1[e]) <= thr) {
                int p = atomicAdd(&s_cnt, 1);
                if (p < CAP) s_cand[p] = (short)(16 * tid + 8 + e);
            }
        }
    }
    __syncthreads();
    const int cnt = min(s_cnt, CAP);

    // exact fp32 re-score: one warp per candidate column (4 cols per group)
    const float4* x4 = reinterpret_cast<const float4*>(X + (size_t)b * K_IN);
    for (int item = wid; item < cnt * 4; item += 8) {
        int j = group_colbase((int)s_cand[item >> 2]) + (item & 3);
        const float4* w4 = reinterpret_cast<const float4*>(W + (size_t)j * K_IN);
        float acc = 0.f;
        #pragma unroll
        for (int i = 0; i < 4; i++) {
            float4 a = x4[lane + i * 32], w = w4[lane + i * 32];
            acc += a.x * w.x + a.y * w.y + a.z * w.z + a.w * w.w;
        }
        #pragma unroll
        for (int o = 16; o > 0; o >>= 1) acc += __shfl_xor_sync(0xFFFFFFFFu, acc, o);
        if (lane == 0) {
            float s = fmaf(-2.f, acc, g_w2[j]);
            unsigned long long p =
                ((unsigned long long)f32_key(s) << 32) | (unsigned int)j;
            atomicMin(&s_best, p);
        }
    }
    __syncthreads();

    // gather grossberg column of the winner
    unsigned int w = (unsigned int)(s_best & 0xFFFFFFFFull);
    for (int o = tid; o < N_OUT; o += 256)
        out[(size_t)b * N_OUT + o] = G[(size_t)o * H_HID + w];
    if (tid == 0 && out_size >= B_BATCH * N_OUT + B_BATCH)
        out[(size_t)B_BATCH * N_OUT + b] = (float)w;
}

// ---------------- launcher (serial; proven structure) ----------------
extern "C" void kernel_launch(void* const* d_in, const int* in_sizes, int n_in,
                              void* d_out, int out_size) {
    const float* x  = (const float*)d_in[0];   // [4096, 512]
    const float* kw = (const float*)d_in[1];   // [16384, 512]
    const float* gw = (const float*)d_in[2];   // [1000, 16384]
    float* out = (float*)d_out;

    cudaFuncSetAttribute(gemm_coarse_kernel,
                         cudaFuncAttributeMaxDynamicSharedMemorySize, GEMM_SMEM);

    prep_kernel<<<(B_BATCH + H_HID) / 8, 256>>>(x, kw);

    dim3 grid(B_BATCH / BM, H_HID / BN);   // (32, 128) = 4096 CTAs
    gemm_coarse_kernel<<<grid, THREADS, GEMM_SMEM>>>();

    refine_gather_kernel<<<B_BATCH, 256>>>(x, kw, gw, out, out_size);
}